// round 1
// baseline (speedup 1.0000x reference)
#include <cuda_runtime.h>

// AttentionBlock fused gate kernel.
// Inputs (metadata order): xatt[B*L*C], xsaut[B*L*C], W_act[C], b_act[1],
//                          W_saut[C], b_saut[1], W2[1], b2[1]
// Output: out[B*L] fp32
//
// B=64, L=16384, C=64 -> N = 1,048,576 positions.
// 16 lanes per position; each lane loads one float4 from each of the two
// input rows (64 floats = 16 float4), dot with the weight float4, reduce
// across the 16-lane group, lane 0 computes the epilogue and stores.

#define NEG_SLOPE 0.3f

__global__ __launch_bounds__(256) void attn_gate_kernel(
    const float* __restrict__ xatt,
    const float* __restrict__ xsaut,
    const float* __restrict__ W_act,
    const float* __restrict__ b_act,
    const float* __restrict__ W_saut,
    const float* __restrict__ b_saut,
    const float* __restrict__ W2,
    const float* __restrict__ b2,
    float* __restrict__ out,
    int n_pos)
{
    const int gtid  = blockIdx.x * blockDim.x + threadIdx.x;
    const int pos   = gtid >> 4;          // 16 lanes per position
    const int lane16 = gtid & 15;
    if (pos >= n_pos) return;

    // Weight float4 for this lane (L1-resident after first touch)
    const float4 wa = __ldg(reinterpret_cast<const float4*>(W_act)  + lane16);
    const float4 ws = __ldg(reinterpret_cast<const float4*>(W_saut) + lane16);

    const float4 a = __ldg(reinterpret_cast<const float4*>(xatt)  + (size_t)pos * 16 + lane16);
    const float4 s = __ldg(reinterpret_cast<const float4*>(xsaut) + (size_t)pos * 16 + lane16);

    float pa = a.x * wa.x + a.y * wa.y + a.z * wa.z + a.w * wa.w;
    float ps = s.x * ws.x + s.y * ws.y + s.z * ws.z + s.w * ws.w;

    // Reduce over the 16-lane group (pairs stay inside the group for offsets < 16)
    #pragma unroll
    for (int off = 8; off > 0; off >>= 1) {
        pa += __shfl_xor_sync(0xFFFFFFFFu, pa, off);
        ps += __shfl_xor_sync(0xFFFFFFFFu, ps, off);
    }

    if (lane16 == 0) {
        const float xa = pa + __ldg(b_act);
        const float xs = ps + __ldg(b_saut);
        float h = xa + xs;
        h = (h >= 0.0f) ? h : NEG_SLOPE * h;
        const float z = h * __ldg(W2) + __ldg(b2);
        const float g = 1.0f / (1.0f + expf(-z));
        out[pos] = g * xs;
    }
}

extern "C" void kernel_launch(void* const* d_in, const int* in_sizes, int n_in,
                              void* d_out, int out_size)
{
    const float* xatt   = (const float*)d_in[0];
    const float* xsaut  = (const float*)d_in[1];
    const float* W_act  = (const float*)d_in[2];
    const float* b_act  = (const float*)d_in[3];
    const float* W_saut = (const float*)d_in[4];
    const float* b_saut = (const float*)d_in[5];
    const float* W2     = (const float*)d_in[6];
    const float* b2     = (const float*)d_in[7];
    float* out = (float*)d_out;

    const int n_pos = out_size;              // B*L = 1,048,576
    const int threads = 256;                 // 16 positions per block
    const int total_threads = n_pos * 16;
    const int blocks = (total_threads + threads - 1) / threads;

    attn_gate_kernel<<<blocks, threads>>>(xatt, xsaut, W_act, b_act,
                                          W_saut, b_saut, W2, b2,
                                          out, n_pos);
}

// round 2
// speedup vs baseline: 1.0369x; 1.0369x over previous
#include <cuda_runtime.h>

// AttentionBlock fused gate kernel, ILP=2.
// Inputs: xatt[B*L*C], xsaut[B*L*C], W_act[C], b_act[1], W_saut[C], b_saut[1], W2[1], b2[1]
// Output: out[B*L] fp32.  B=64, L=16384, C=64 -> n_pos = 1,048,576.
//
// 16 lanes per position-pair; each lane loads one float4 from each of the two
// input rows for TWO positions (pos and pos + n_pos/2), giving 4 independent
// LDG.128 in flight per thread. Reduce across the 16-lane group via shuffles,
// lane 0 does the scalar epilogue for both positions.

#define NEG_SLOPE 0.3f

__global__ __launch_bounds__(256) void attn_gate_kernel(
    const float* __restrict__ xatt,
    const float* __restrict__ xsaut,
    const float* __restrict__ W_act,
    const float* __restrict__ b_act,
    const float* __restrict__ W_saut,
    const float* __restrict__ b_saut,
    const float* __restrict__ W2,
    const float* __restrict__ b2,
    float* __restrict__ out,
    int n_pos)
{
    const int gtid   = blockIdx.x * blockDim.x + threadIdx.x;
    const int pos0   = gtid >> 4;          // 16 lanes per position
    const int lane16 = gtid & 15;
    const int half   = n_pos >> 1;
    if (pos0 >= half) return;
    const int pos1 = pos0 + half;

    // Weight float4 for this lane (L1-resident after first touch)
    const float4 wa = __ldg(reinterpret_cast<const float4*>(W_act)  + lane16);
    const float4 ws = __ldg(reinterpret_cast<const float4*>(W_saut) + lane16);

    // Front-batch 4 independent global loads (MLP=4)
    const float4 a0 = __ldg(reinterpret_cast<const float4*>(xatt)  + (size_t)pos0 * 16 + lane16);
    const float4 s0 = __ldg(reinterpret_cast<const float4*>(xsaut) + (size_t)pos0 * 16 + lane16);
    const float4 a1 = __ldg(reinterpret_cast<const float4*>(xatt)  + (size_t)pos1 * 16 + lane16);
    const float4 s1 = __ldg(reinterpret_cast<const float4*>(xsaut) + (size_t)pos1 * 16 + lane16);

    float pa0 = a0.x * wa.x + a0.y * wa.y + a0.z * wa.z + a0.w * wa.w;
    float ps0 = s0.x * ws.x + s0.y * ws.y + s0.z * ws.z + s0.w * ws.w;
    float pa1 = a1.x * wa.x + a1.y * wa.y + a1.z * wa.z + a1.w * wa.w;
    float ps1 = s1.x * ws.x + s1.y * ws.y + s1.z * ws.z + s1.w * ws.w;

    // Reduce over the 16-lane group (offsets < 16 stay inside the group)
    #pragma unroll
    for (int off = 8; off > 0; off >>= 1) {
        pa0 += __shfl_xor_sync(0xFFFFFFFFu, pa0, off);
        ps0 += __shfl_xor_sync(0xFFFFFFFFu, ps0, off);
        pa1 += __shfl_xor_sync(0xFFFFFFFFu, pa1, off);
        ps1 += __shfl_xor_sync(0xFFFFFFFFu, ps1, off);
    }

    if (lane16 == 0) {
        const float ba = __ldg(b_act);
        const float bs = __ldg(b_saut);
        const float w2 = __ldg(W2);
        const float bb = __ldg(b2);

        {
            const float xs = ps0 + bs;
            float h = (pa0 + ba) + xs;
            h = (h >= 0.0f) ? h : NEG_SLOPE * h;
            const float z = h * w2 + bb;
            out[pos0] = xs / (1.0f + expf(-z));
        }
        {
            const float xs = ps1 + bs;
            float h = (pa1 + ba) + xs;
            h = (h >= 0.0f) ? h : NEG_SLOPE * h;
            const float z = h * w2 + bb;
            out[pos1] = xs / (1.0f + expf(-z));
        }
    }
}

extern "C" void kernel_launch(void* const* d_in, const int* in_sizes, int n_in,
                              void* d_out, int out_size)
{
    const float* xatt   = (const float*)d_in[0];
    const float* xsaut  = (const float*)d_in[1];
    const float* W_act  = (const float*)d_in[2];
    const float* b_act  = (const float*)d_in[3];
    const float* W_saut = (const float*)d_in[4];
    const float* b_saut = (const float*)d_in[5];
    const float* W2     = (const float*)d_in[6];
    const float* b2     = (const float*)d_in[7];
    float* out = (float*)d_out;

    const int n_pos = out_size;              // B*L = 1,048,576 (even)
    const int threads = 256;
    const long long total_threads = (long long)(n_pos / 2) * 16;
    const int blocks = (int)((total_threads + threads - 1) / threads);

    attn_gate_kernel<<<blocks, threads>>>(xatt, xsaut, W_act, b_act,
                                          W_saut, b_saut, W2, b2,
                                          out, n_pos);
}